// round 2
// baseline (speedup 1.0000x reference)
#include <cuda_runtime.h>
#include <cstdint>

// Problem constants (shapes fixed by the dataset)
#define BATCH    2
#define Hh       64
#define Ww       64
#define Cc       128
#define HO       32
#define WO       32
#define NPOOL    131072           // HO*WO*C per batch
#define NOUT     32
#define NIN      524288           // H*W*C per batch  (64*64*128)
#define WZ       33554432LL       // BATCH*NIN*NOUT   (one w_zero tensor, both batches)
#define OFF_BU   (WZ)             // 64 floats
#define OFF_BL   (2*WZ + 64)      // 64 floats
#define TOTAL    (2*WZ + 128)     // 67,108,992 floats = 268 MB

#define RBLKS    64               // reduction blocks per batch

// Scratch (no device allocs allowed)
__device__ float g_bu[BATCH * NPOOL];
__device__ float g_bl[BATCH * NPOOL];
__device__ float g_pu[BATCH * RBLKS * NOUT];
__device__ float g_pl[BATCH * RBLKS * NOUT];

// ---------------------------------------------------------------------------
// 1) Zero-fill the whole output (67,108,992 f32 = 16,777,248 float4)
// ---------------------------------------------------------------------------
__global__ void zero_kernel(float4* __restrict__ out, long long n4) {
    long long i = (long long)blockIdx.x * blockDim.x + threadIdx.x;
    long long stride = (long long)gridDim.x * blockDim.x;
    float4 z = make_float4(0.f, 0.f, 0.f, 0.f);
    for (; i < n4; i += stride) out[i] = z;
}

// ---------------------------------------------------------------------------
// 2) 2x2 maxpool (VALID, stride 2) of the interval bounds, NHWC.
//    Since l_c < u_c elementwise, pool(elementwise max) == pool(u_c) and
//    pool(elementwise min) == pool(l_c) — order-robust, same load count.
//    p = (oh*WO + ow)*C + c
// ---------------------------------------------------------------------------
__global__ void pool_kernel(const float* __restrict__ a,
                            const float* __restrict__ b) {
    int idx = blockIdx.x * blockDim.x + threadIdx.x;
    if (idx >= BATCH * NPOOL) return;
    int bb = idx >> 17;            // /NPOOL (2^17)
    int p  = idx & (NPOOL - 1);
    int c  = p & (Cc - 1);
    int ow = (p >> 7) & (WO - 1);
    int oh = p >> 12;
    size_t base = (((size_t)bb * Hh + oh * 2) * Ww + ow * 2) * Cc + c;
    const size_t rs = (size_t)Ww * Cc;   // 8192

    float mu = -3.4e38f, ml = 3.4e38f;
    #pragma unroll
    for (int k = 0; k < 4; k++) {
        size_t off = base + (k >> 1) * rs + (k & 1) * Cc;
        float x = a[off], y = b[off];
        mu = fmaxf(mu, fmaxf(x, y));
        ml = fminf(ml, fminf(x, y));
    }
    // Wait: ml must be pool-of-min = MAX over window of elementwise-min.
    // (fixed below — see pool2)
    g_bu[idx] = mu;
    g_bl[idx] = ml;   // placeholder, overwritten by correct logic in pool2 path
}

// Correct version: bu = max over window of max(x,y); bl = max over window of min(x,y)
__global__ void pool2_kernel(const float* __restrict__ a,
                             const float* __restrict__ b) {
    int idx = blockIdx.x * blockDim.x + threadIdx.x;
    if (idx >= BATCH * NPOOL) return;
    int bb = idx >> 17;
    int p  = idx & (NPOOL - 1);
    int c  = p & (Cc - 1);
    int ow = (p >> 7) & (WO - 1);
    int oh = p >> 12;
    size_t base = (((size_t)bb * Hh + oh * 2) * Ww + ow * 2) * Cc + c;
    const size_t rs = (size_t)Ww * Cc;

    float mu = -3.4e38f, ml = -3.4e38f;
    #pragma unroll
    for (int k = 0; k < 4; k++) {
        size_t off = base + (k >> 1) * rs + (k & 1) * Cc;
        float x = a[off], y = b[off];
        mu = fmaxf(mu, fmaxf(x, y));   // window-max of u_c
        ml = fmaxf(ml, fminf(x, y));   // window-max of l_c
    }
    g_bu[idx] = mu;
    g_bl[idx] = ml;
}

// ---------------------------------------------------------------------------
// 3) Partial reductions over p for both u and l channels.
//    grid = BATCH*RBLKS blocks, 256 threads (8 warps). lane = output col j.
//    w layout: w[b][p][j], j contiguous -> 32-lane warp load = one 128B line.
//    max(w,0)*bu + min(w,0)*bl == w * (w>=0 ? bu : bl)
// ---------------------------------------------------------------------------
__global__ void partial_kernel(const float* __restrict__ wu,
                               const float* __restrict__ wl) {
    int blk  = blockIdx.x;
    int b    = blk / RBLKS;
    int cb   = blk % RBLKS;
    int warp = threadIdx.x >> 5;
    int lane = threadIdx.x & 31;

    const float* __restrict__ bu  = g_bu + b * NPOOL;
    const float* __restrict__ bl  = g_bl + b * NPOOL;
    const float* __restrict__ wub = wu + (size_t)b * NPOOL * NOUT;
    const float* __restrict__ wlb = wl + (size_t)b * NPOOL * NOUT;

    const int P_PER_BLK = NPOOL / RBLKS;       // 2048
    int p0 = cb * P_PER_BLK;

    float au = 0.f, al = 0.f;
    #pragma unroll 4
    for (int k = 0; k < P_PER_BLK / 8; k++) {
        int p = p0 + k * 8 + warp;
        float u = __ldg(&bu[p]);
        float l = __ldg(&bl[p]);
        float a = __ldg(&wub[(size_t)p * NOUT + lane]);
        float c = __ldg(&wlb[(size_t)p * NOUT + lane]);
        au += a * (a >= 0.f ? u : l);
        al += c * (c >= 0.f ? l : u);
    }

    __shared__ float su[8][32];
    __shared__ float sl[8][32];
    su[warp][lane] = au;
    sl[warp][lane] = al;
    __syncthreads();

    if (warp == 0) {
        float s1 = 0.f, s2 = 0.f;
        #pragma unroll
        for (int i = 0; i < 8; i++) { s1 += su[i][lane]; s2 += sl[i][lane]; }
        g_pu[(b * RBLKS + cb) * NOUT + lane] = s1;
        g_pl[(b * RBLKS + cb) * NOUT + lane] = s2;
    }
}

// ---------------------------------------------------------------------------
// 4) Final reduce across RBLKS partials + bias add; writes the 128 bias floats.
// ---------------------------------------------------------------------------
__global__ void final_kernel(const float* __restrict__ bou,
                             const float* __restrict__ bol,
                             float* __restrict__ out) {
    int t = threadIdx.x;                 // 0..63
    if (t >= BATCH * NOUT) return;
    int b = t >> 5;
    int j = t & 31;
    float su = 0.f, sl = 0.f;
    #pragma unroll 8
    for (int k = 0; k < RBLKS; k++) {
        su += g_pu[(b * RBLKS + k) * NOUT + j];
        sl += g_pl[(b * RBLKS + k) * NOUT + j];
    }
    out[OFF_BU + b * NOUT + j] = su + bou[b * NOUT + j];
    out[OFF_BL + b * NOUT + j] = sl + bol[b * NOUT + j];
}

// ---------------------------------------------------------------------------
// Inputs (metadata order): y, x_0, u_c, l_c, w_out_u, b_out_u, w_out_l, b_out_l
// Output: concat of [w_zero (WZ), b_out_u_ (64), w_zero (WZ), b_out_l_ (64)]
// ---------------------------------------------------------------------------
extern "C" void kernel_launch(void* const* d_in, const int* in_sizes, int n_in,
                              void* d_out, int out_size) {
    const float* u_c  = (const float*)d_in[2];
    const float* l_c  = (const float*)d_in[3];
    const float* wu   = (const float*)d_in[4];
    const float* bou  = (const float*)d_in[5];
    const float* wl   = (const float*)d_in[6];
    const float* bol  = (const float*)d_in[7];
    float* out = (float*)d_out;

    // 1) zero everything (268 MB) — the dominant cost
    long long n4 = (long long)out_size / 4;
    zero_kernel<<<2368, 256>>>((float4*)out, n4);

    // 2) maxpool bounds into scratch (order-robust elementwise min/max form)
    pool2_kernel<<<(BATCH * NPOOL + 255) / 256, 256>>>(u_c, l_c);

    // 3) partial interval reductions
    partial_kernel<<<BATCH * RBLKS, 256>>>(wu, wl);

    // 4) final bias values
    final_kernel<<<1, 64>>>(bou, bol, out);
}

// round 3
// speedup vs baseline: 1.3978x; 1.3978x over previous
#include <cuda_runtime.h>
#include <cstdint>

// Problem constants (shapes fixed by the dataset)
#define BATCH    2
#define Hh       64
#define Ww       64
#define Cc       128
#define HO       32
#define WO       32
#define NPOOL    131072           // HO*WO*C per batch
#define NOUT     32
#define NIN      524288           // H*W*C per batch  (64*64*128)
#define WZ       33554432LL       // BATCH*NIN*NOUT (one w_zero tensor, both batches)
#define OFF_BU   (WZ)             // 64 floats
#define OFF_BL   (2*WZ + 64)      // 64 floats
#define TOTAL    (2*WZ + 128)     // 67,108,992 floats = 268 MB

#define RBLKS    128              // reduction blocks per batch
#define RB       (BATCH * RBLKS)  // 256 reduce blocks
#define ZB       2048             // zero-fill blocks
#define NTHREADS 256

// Scratch (no device allocs allowed)
__device__ float g_pu[BATCH * RBLKS * NOUT];
__device__ float g_pl[BATCH * RBLKS * NOUT];

// ---------------------------------------------------------------------------
// Mega kernel: blocks [0, RB) do the interval reduction with inline 2x2 pool;
// blocks [RB, RB+ZB) zero-fill the 268 MB output.
// ---------------------------------------------------------------------------
__global__ void __launch_bounds__(NTHREADS)
mega_kernel(const float* __restrict__ uc,
            const float* __restrict__ lc,
            const float* __restrict__ wu,
            const float* __restrict__ wl,
            float4* __restrict__ out4, long long n4) {
    int blk = blockIdx.x;

    if (blk >= RB) {
        // ---- zero-fill role ----
        long long i = (long long)(blk - RB) * NTHREADS + threadIdx.x;
        const long long stride = (long long)ZB * NTHREADS;
        float4 z = make_float4(0.f, 0.f, 0.f, 0.f);
        for (; i < n4; i += stride) out4[i] = z;
        return;
    }

    // ---- reduction role ----
    int b    = blk >> 7;              // / RBLKS
    int cb   = blk & (RBLKS - 1);
    int warp = threadIdx.x >> 5;
    int lane = threadIdx.x & 31;

    const float* __restrict__ ucb = uc + (size_t)b * NIN;
    const float* __restrict__ lcb = lc + (size_t)b * NIN;
    const float* __restrict__ wub = wu + (size_t)b * NPOOL * NOUT;
    const float* __restrict__ wlb = wl + (size_t)b * NPOOL * NOUT;

    const int P_PER_BLK = NPOOL / RBLKS;   // 1024
    int p0 = cb * P_PER_BLK;

    const size_t rs = (size_t)Ww * Cc;     // 8192

    float au = 0.f, al = 0.f;
    #pragma unroll 2
    for (int k = 0; k < P_PER_BLK / 8; k++) {
        int p = p0 + k * 8 + warp;
        // inline 2x2 maxpool of both bounds (broadcast loads within warp)
        int c  = p & (Cc - 1);
        int ow = (p >> 7) & (WO - 1);
        int oh = p >> 12;
        size_t base = (((size_t)oh * 2) * Ww + ow * 2) * Cc + c;
        float u0 = __ldg(&ucb[base]),        l0 = __ldg(&lcb[base]);
        float u1 = __ldg(&ucb[base + Cc]),   l1 = __ldg(&lcb[base + Cc]);
        float u2 = __ldg(&ucb[base + rs]),   l2 = __ldg(&lcb[base + rs]);
        float u3 = __ldg(&ucb[base + rs + Cc]), l3 = __ldg(&lcb[base + rs + Cc]);
        float bu = fmaxf(fmaxf(u0, u1), fmaxf(u2, u3));
        float bl = fmaxf(fmaxf(l0, l1), fmaxf(l2, l3));

        // coalesced weight loads: lane = output column j
        float a = __ldg(&wub[(size_t)p * NOUT + lane]);
        float c2 = __ldg(&wlb[(size_t)p * NOUT + lane]);
        // max(w,0)*bu + min(w,0)*bl == w * (w>=0 ? bu : bl)
        au += a  * (a  >= 0.f ? bu : bl);
        al += c2 * (c2 >= 0.f ? bl : bu);
    }

    __shared__ float su[8][32];
    __shared__ float sl[8][32];
    su[warp][lane] = au;
    sl[warp][lane] = al;
    __syncthreads();

    if (warp == 0) {
        float s1 = 0.f, s2 = 0.f;
        #pragma unroll
        for (int i = 0; i < 8; i++) { s1 += su[i][lane]; s2 += sl[i][lane]; }
        g_pu[(b * RBLKS + cb) * NOUT + lane] = s1;
        g_pl[(b * RBLKS + cb) * NOUT + lane] = s2;
    }
}

// ---------------------------------------------------------------------------
// Final reduce across RBLKS partials + bias add; writes the 128 bias floats.
// 512 threads: t -> (kgroup, b, j); each sums 16 partials, then smem tree.
// ---------------------------------------------------------------------------
__global__ void final_kernel(const float* __restrict__ bou,
                             const float* __restrict__ bol,
                             float* __restrict__ out) {
    int t  = threadIdx.x;          // 0..511
    int j  = t & 31;
    int b  = (t >> 5) & 1;
    int kg = t >> 6;               // 0..7
    float su = 0.f, sl = 0.f;
    #pragma unroll
    for (int k = kg * 16; k < kg * 16 + 16; k++) {
        su += g_pu[(b * RBLKS + k) * NOUT + j];
        sl += g_pl[(b * RBLKS + k) * NOUT + j];
    }
    __shared__ float shu[8][64];
    __shared__ float shl[8][64];
    shu[kg][b * 32 + j] = su;
    shl[kg][b * 32 + j] = sl;
    __syncthreads();
    if (kg == 0) {
        float a = 0.f, c = 0.f;
        #pragma unroll
        for (int i = 0; i < 8; i++) { a += shu[i][b * 32 + j]; c += shl[i][b * 32 + j]; }
        out[OFF_BU + b * NOUT + j] = a + __ldg(&bou[b * NOUT + j]);
        out[OFF_BL + b * NOUT + j] = c + __ldg(&bol[b * NOUT + j]);
    }
}

// ---------------------------------------------------------------------------
// Inputs (metadata order): y, x_0, u_c, l_c, w_out_u, b_out_u, w_out_l, b_out_l
// Output: concat of [w_zero (WZ), b_out_u_ (64), w_zero (WZ), b_out_l_ (64)]
// ---------------------------------------------------------------------------
extern "C" void kernel_launch(void* const* d_in, const int* in_sizes, int n_in,
                              void* d_out, int out_size) {
    const float* u_c  = (const float*)d_in[2];
    const float* l_c  = (const float*)d_in[3];
    const float* wu   = (const float*)d_in[4];
    const float* bou  = (const float*)d_in[5];
    const float* wl   = (const float*)d_in[6];
    const float* bol  = (const float*)d_in[7];
    float* out = (float*)d_out;

    long long n4 = (long long)out_size / 4;
    mega_kernel<<<RB + ZB, NTHREADS>>>(u_c, l_c, wu, wl, (float4*)out, n4);
    final_kernel<<<1, 512>>>(bou, bol, out);
}

// round 5
// speedup vs baseline: 1.5748x; 1.1266x over previous
#include <cuda_runtime.h>
#include <cstdint>

// Problem constants (shapes fixed by the dataset)
#define BATCH    2
#define Hh       64
#define Ww       64
#define Cc       128
#define HO       32
#define WO       32
#define NPOOL    131072           // HO*WO*C per batch
#define NOUT     32
#define NIN      524288           // H*W*C per batch  (64*64*128)
#define WZ       33554432LL       // BATCH*NIN*NOUT (one w_zero tensor)
#define OFF_BU   (WZ)             // 64 floats
#define OFF_BL   (2*WZ + 64)      // 64 floats

#define RBLKS    128              // reduction blocks per batch
#define RB       (BATCH * RBLKS)  // 256 reduce blocks
#define ZB       2048             // zero-fill blocks
#define NTHREADS 256

// float4-index windows holding the bias outputs (skipped by fill)
#define SK1      (WZ / 4)                 // 8388608
#define SK2      ((2*WZ + 64) / 4)        // 16777232

// Scratch (no device allocs allowed)
__device__ float g_pu[RB * NOUT];
__device__ float g_pl[RB * NOUT];
__device__ unsigned int g_ctr = 0;

__global__ void __launch_bounds__(NTHREADS)
mega_kernel(const float* __restrict__ uc,
            const float* __restrict__ lc,
            const float* __restrict__ wu,
            const float* __restrict__ wl,
            const float* __restrict__ bou,
            const float* __restrict__ bol,
            float4* __restrict__ out4, long long n4) {
    int blk = blockIdx.x;

    if (blk >= RB) {
        // ---------------- zero-fill role (streaming stores, skip bias words) ----
        const long long stride = (long long)ZB * NTHREADS;
        long long i = (long long)(blk - RB) * NTHREADS + threadIdx.x;
        float4 z = make_float4(0.f, 0.f, 0.f, 0.f);
        for (; i + 3 * stride < n4; i += 4 * stride) {
            long long i0 = i, i1 = i + stride, i2 = i + 2 * stride, i3 = i + 3 * stride;
            if ((unsigned long long)(i0 - SK1) >= 16ULL && (unsigned long long)(i0 - SK2) >= 16ULL)
                __stcs(&out4[i0], z);
            if ((unsigned long long)(i1 - SK1) >= 16ULL && (unsigned long long)(i1 - SK2) >= 16ULL)
                __stcs(&out4[i1], z);
            if ((unsigned long long)(i2 - SK1) >= 16ULL && (unsigned long long)(i2 - SK2) >= 16ULL)
                __stcs(&out4[i2], z);
            if ((unsigned long long)(i3 - SK1) >= 16ULL && (unsigned long long)(i3 - SK2) >= 16ULL)
                __stcs(&out4[i3], z);
        }
        for (; i < n4; i += stride) {
            if ((unsigned long long)(i - SK1) >= 16ULL && (unsigned long long)(i - SK2) >= 16ULL)
                __stcs(&out4[i], z);
        }
        return;
    }

    // ---------------- reduction role ----------------
    int b    = blk >> 7;              // / RBLKS
    int cb   = blk & (RBLKS - 1);
    int warp = threadIdx.x >> 5;
    int lane = threadIdx.x & 31;

    const float* __restrict__ ucb = uc + (size_t)b * NIN;
    const float* __restrict__ lcb = lc + (size_t)b * NIN;
    const float* __restrict__ wub = wu + (size_t)b * NPOOL * NOUT;
    const float* __restrict__ wlb = wl + (size_t)b * NPOOL * NOUT;

    const int P_PER_BLK = NPOOL / RBLKS;   // 1024
    int p0 = cb * P_PER_BLK;
    const size_t rs = (size_t)Ww * Cc;     // 8192

    float au = 0.f, al = 0.f;
    #pragma unroll 4
    for (int k = 0; k < P_PER_BLK / 8; k++) {
        int p = p0 + k * 8 + warp;
        // inline 2x2 maxpool of both bounds (broadcast loads, L2-resident)
        int c  = p & (Cc - 1);
        int ow = (p >> 7) & (WO - 1);
        int oh = p >> 12;
        size_t base = (((size_t)oh * 2) * Ww + ow * 2) * Cc + c;
        float u0 = __ldg(&ucb[base]),           l0 = __ldg(&lcb[base]);
        float u1 = __ldg(&ucb[base + Cc]),      l1 = __ldg(&lcb[base + Cc]);
        float u2 = __ldg(&ucb[base + rs]),      l2 = __ldg(&lcb[base + rs]);
        float u3 = __ldg(&ucb[base + rs + Cc]), l3 = __ldg(&lcb[base + rs + Cc]);
        float bu = fmaxf(fmaxf(u0, u1), fmaxf(u2, u3));
        float bl = fmaxf(fmaxf(l0, l1), fmaxf(l2, l3));

        // streaming weight loads: lane = output column j (128B coalesced)
        float a  = __ldcs(&wub[(size_t)p * NOUT + lane]);
        float c2 = __ldcs(&wlb[(size_t)p * NOUT + lane]);
        // max(w,0)*bu + min(w,0)*bl == w * (w>=0 ? bu : bl)
        au += a  * (a  >= 0.f ? bu : bl);
        al += c2 * (c2 >= 0.f ? bl : bu);
    }

    __shared__ float su[8][32];
    __shared__ float sl[8][32];
    su[warp][lane] = au;
    sl[warp][lane] = al;
    __syncthreads();

    __shared__ bool s_last;
    if (threadIdx.x == 0) s_last = false;
    if (warp == 0) {
        float s1 = 0.f, s2 = 0.f;
        #pragma unroll
        for (int i = 0; i < 8; i++) { s1 += su[i][lane]; s2 += sl[i][lane]; }
        g_pu[blk * NOUT + lane] = s1;
        g_pl[blk * NOUT + lane] = s2;
    }
    __syncthreads();           // partial writes done block-wide
    if (threadIdx.x == 0) {
        __threadfence();       // release partials
        unsigned int prev = atomicAdd(&g_ctr, 1u);
        if (prev == RB - 1) s_last = true;
    }
    __syncthreads();
    if (!s_last) return;

    // ---------------- last block: final reduce + bias writes ----------------
    __threadfence();           // acquire all partials
    {
        int t  = threadIdx.x;          // 0..255
        int j  = t & 31;
        int bb = (t >> 5) & 1;
        int kg = t >> 6;               // 0..3
        float s1 = 0.f, s2 = 0.f;
        #pragma unroll 8
        for (int k = kg * 32; k < kg * 32 + 32; k++) {
            s1 += g_pu[(bb * RBLKS + k) * NOUT + j];
            s2 += g_pl[(bb * RBLKS + k) * NOUT + j];
        }
        __shared__ float shu[4][64];
        __shared__ float shl[4][64];
        shu[kg][bb * 32 + j] = s1;
        shl[kg][bb * 32 + j] = s2;
        __syncthreads();
        if (kg == 0) {
            float a = 0.f, c = 0.f;
            #pragma unroll
            for (int i = 0; i < 4; i++) { a += shu[i][bb * 32 + j]; c += shl[i][bb * 32 + j]; }
            float* out = (float*)out4;
            out[OFF_BU + bb * NOUT + j] = a + __ldg(&bou[bb * NOUT + j]);
            out[OFF_BL + bb * NOUT + j] = c + __ldg(&bol[bb * NOUT + j]);
        }
        if (threadIdx.x == 0) g_ctr = 0;   // reset for next graph replay
    }
}

// ---------------------------------------------------------------------------
// Inputs (metadata order): y, x_0, u_c, l_c, w_out_u, b_out_u, w_out_l, b_out_l
// Output: concat of [w_zero (WZ), b_out_u_ (64), w_zero (WZ), b_out_l_ (64)]
// ---------------------------------------------------------------------------
extern "C" void kernel_launch(void* const* d_in, const int* in_sizes, int n_in,
                              void* d_out, int out_size) {
    const float* u_c  = (const float*)d_in[2];
    const float* l_c  = (const float*)d_in[3];
    const float* wu   = (const float*)d_in[4];
    const float* bou  = (const float*)d_in[5];
    const float* wl   = (const float*)d_in[6];
    const float* bol  = (const float*)d_in[7];

    long long n4 = (long long)out_size / 4;
    mega_kernel<<<RB + ZB, NTHREADS>>>(u_c, l_c, wu, wl, bou, bol,
                                       (float4*)d_out, n4);
}

// round 7
// speedup vs baseline: 2.2993x; 1.4600x over previous
#include <cuda_runtime.h>
#include <cstdint>

// Problem constants (shapes fixed by the dataset)
#define BATCH    2
#define Hh       64
#define Ww       64
#define Cc       128
#define HO       32
#define WO       32
#define NPOOL    131072           // HO*WO*C per batch
#define NOUT     32
#define NIN      524288           // H*W*C per batch  (64*64*128)
#define WZ       33554432LL       // BATCH*NIN*NOUT (one w_zero tensor)
#define OFF_BU   (WZ)             // 64 floats
#define OFF_BL   (2*WZ + 64)      // 64 floats

#define RBLKS    512              // reduction blocks per batch
#define RB       (BATCH * RBLKS)  // 1024 reduce blocks
#define NTHREADS 256

// Scratch (no device allocs allowed)
__device__ float g_pu[RB * NOUT];
__device__ float g_pl[RB * NOUT];
__device__ unsigned int g_ctr = 0;

// ---------------------------------------------------------------------------
// Reduction kernel. 1024 blocks x 256 threads.
// Warp layout: 4 p-values per warp-iteration; lane -> (pg = lane>>3, j0 = (lane&7)*4).
// Each lane loads w[p][j0..j0+3] as float4 (LDG.128, fully coalesced: a warp
// covers 4 consecutive p rows x 32 j = 512B) and the pooled bounds for its p
// (broadcast among 8 lanes, L1/L2-resident: pool inputs are only 8 MB).
// max(w,0)*bu + min(w,0)*bl == w * (w>=0 ? bu : bl).
// Last block (counter) does the final reduce + bias writes.
// ---------------------------------------------------------------------------
__global__ void __launch_bounds__(NTHREADS)
reduce_kernel(const float* __restrict__ uc,
              const float* __restrict__ lc,
              const float* __restrict__ wu,
              const float* __restrict__ wl,
              const float* __restrict__ bou,
              const float* __restrict__ bol,
              float* __restrict__ out) {
    int blk  = blockIdx.x;
    int b    = blk >> 9;               // / RBLKS
    int cb   = blk & (RBLKS - 1);
    int warp = threadIdx.x >> 5;
    int lane = threadIdx.x & 31;
    int pg   = lane >> 3;              // 0..3: which p in the group of 4
    int j0   = (lane & 7) * 4;         // 4 output columns per lane

    const float* __restrict__ ucb = uc + (size_t)b * NIN;
    const float* __restrict__ lcb = lc + (size_t)b * NIN;
    const float* __restrict__ wub = wu + (size_t)b * NPOOL * NOUT;
    const float* __restrict__ wlb = wl + (size_t)b * NPOOL * NOUT;

    const int P_PER_BLK  = NPOOL / RBLKS;    // 256
    const int P_PER_WARP = P_PER_BLK / 8;    // 32
    int p0 = cb * P_PER_BLK + warp * P_PER_WARP;
    const size_t rs = (size_t)Ww * Cc;       // 8192

    float au0 = 0.f, au1 = 0.f, au2 = 0.f, au3 = 0.f;
    float al0 = 0.f, al1 = 0.f, al2 = 0.f, al3 = 0.f;

    #pragma unroll 4
    for (int it = 0; it < P_PER_WARP / 4; it++) {   // 8 iters, 4 p each
        int p = p0 + it * 4 + pg;
        // inline 2x2 maxpool for this p
        int c  = p & (Cc - 1);
        int ow = (p >> 7) & (WO - 1);
        int oh = p >> 12;
        size_t base = (((size_t)oh * 2) * Ww + ow * 2) * Cc + c;
        float u0 = __ldg(&ucb[base]),           l0 = __ldg(&lcb[base]);
        float u1 = __ldg(&ucb[base + Cc]),      l1 = __ldg(&lcb[base + Cc]);
        float u2 = __ldg(&ucb[base + rs]),      l2 = __ldg(&lcb[base + rs]);
        float u3 = __ldg(&ucb[base + rs + Cc]), l3 = __ldg(&lcb[base + rs + Cc]);
        float bu = fmaxf(fmaxf(u0, u1), fmaxf(u2, u3));
        float bl = fmaxf(fmaxf(l0, l1), fmaxf(l2, l3));

        // wide streaming weight loads
        size_t wbase = (size_t)p * NOUT + j0;
        float4 a  = __ldcs((const float4*)&wub[wbase]);
        float4 c4 = __ldcs((const float4*)&wlb[wbase]);
        au0 += a.x  * (a.x  >= 0.f ? bu : bl);
        au1 += a.y  * (a.y  >= 0.f ? bu : bl);
        au2 += a.z  * (a.z  >= 0.f ? bu : bl);
        au3 += a.w  * (a.w  >= 0.f ? bu : bl);
        al0 += c4.x * (c4.x >= 0.f ? bl : bu);
        al1 += c4.y * (c4.y >= 0.f ? bl : bu);
        al2 += c4.z * (c4.z >= 0.f ? bl : bu);
        al3 += c4.w * (c4.w >= 0.f ? bl : bu);
    }

    // combine the 4 p-groups (lanes l, l+8, l+16, l+24 share the same j's)
    #pragma unroll
    for (int ofs = 8; ofs < 32; ofs <<= 1) {
        au0 += __shfl_xor_sync(0xffffffffu, au0, ofs);
        au1 += __shfl_xor_sync(0xffffffffu, au1, ofs);
        au2 += __shfl_xor_sync(0xffffffffu, au2, ofs);
        au3 += __shfl_xor_sync(0xffffffffu, au3, ofs);
        al0 += __shfl_xor_sync(0xffffffffu, al0, ofs);
        al1 += __shfl_xor_sync(0xffffffffu, al1, ofs);
        al2 += __shfl_xor_sync(0xffffffffu, al2, ofs);
        al3 += __shfl_xor_sync(0xffffffffu, al3, ofs);
    }

    __shared__ float su[8][32];
    __shared__ float sl[8][32];
    if (lane < 8) {
        su[warp][j0 + 0] = au0; su[warp][j0 + 1] = au1;
        su[warp][j0 + 2] = au2; su[warp][j0 + 3] = au3;
        sl[warp][j0 + 0] = al0; sl[warp][j0 + 1] = al1;
        sl[warp][j0 + 2] = al2; sl[warp][j0 + 3] = al3;
    }
    __syncthreads();

    __shared__ bool s_last;
    if (threadIdx.x == 0) s_last = false;
    if (warp == 0) {
        float s1 = 0.f, s2 = 0.f;
        #pragma unroll
        for (int i = 0; i < 8; i++) { s1 += su[i][lane]; s2 += sl[i][lane]; }
        g_pu[blk * NOUT + lane] = s1;
        g_pl[blk * NOUT + lane] = s2;
    }
    __syncthreads();
    if (threadIdx.x == 0) {
        __threadfence();       // release partials
        unsigned int prev = atomicAdd(&g_ctr, 1u);
        if (prev == RB - 1) s_last = true;
    }
    __syncthreads();
    if (!s_last) return;

    // ---------------- last block: final reduce + bias writes ----------------
    __threadfence();           // acquire all partials
    {
        int t  = threadIdx.x;          // 0..255
        int j  = t & 31;
        int bb = (t >> 5) & 1;
        int kg = t >> 6;               // 0..3 -> 128 partials each
        float s1 = 0.f, s2 = 0.f;
        #pragma unroll 8
        for (int k = kg * 128; k < kg * 128 + 128; k++) {
            s1 += g_pu[(bb * RBLKS + k) * NOUT + j];
            s2 += g_pl[(bb * RBLKS + k) * NOUT + j];
        }
        __shared__ float shu[4][64];
        __shared__ float shl[4][64];
        shu[kg][bb * 32 + j] = s1;
        shl[kg][bb * 32 + j] = s2;
        __syncthreads();
        if (kg == 0) {
            float a = 0.f, c = 0.f;
            #pragma unroll
            for (int i = 0; i < 4; i++) { a += shu[i][bb * 32 + j]; c += shl[i][bb * 32 + j]; }
            out[OFF_BU + bb * NOUT + j] = a + __ldg(&bou[bb * NOUT + j]);
            out[OFF_BL + bb * NOUT + j] = c + __ldg(&bol[bb * NOUT + j]);
        }
        if (threadIdx.x == 0) g_ctr = 0;   // reset for next graph replay
    }
}

// ---------------------------------------------------------------------------
// Inputs (metadata order): y, x_0, u_c, l_c, w_out_u, b_out_u, w_out_l, b_out_l
// Output: concat of [w_zero (WZ), b_out_u_ (64), w_zero (WZ), b_out_l_ (64)]
// ---------------------------------------------------------------------------
extern "C" void kernel_launch(void* const* d_in, const int* in_sizes, int n_in,
                              void* d_out, int out_size) {
    const float* u_c  = (const float*)d_in[2];
    const float* l_c  = (const float*)d_in[3];
    const float* wu   = (const float*)d_in[4];
    const float* bou  = (const float*)d_in[5];
    const float* wl   = (const float*)d_in[6];
    const float* bol  = (const float*)d_in[7];

    // 1) driver-optimized zero fill of the entire 268 MB output (memset node;
    //    graph-capturable, no allocation)
    cudaMemsetAsync(d_out, 0, (size_t)out_size * sizeof(float), 0);

    // 2) interval reduction + bias writes (after memset in stream order)
    reduce_kernel<<<RB, NTHREADS>>>(u_c, l_c, wu, wl, bou, bol, (float*)d_out);
}